// round 8
// baseline (speedup 1.0000x reference)
#include <cuda_runtime.h>
#include <cuda_bf16.h>

// Problem shapes (fixed by dataset)
#define KK 2048   // batch/k dim
#define MM 512    // feature dim m
#define NN 64     // target dim n
#define EPSV 1e-8f
#define LMAX 32
#define NCHUNK 4
#define KCH (KK / NCHUNK)   // 512 k-rows per chunk

// ---------------- scratch (static device globals; no allocation) ----------------
__device__ float g_S[KK * MM];     // logits x @ w_att
__device__ float g_soft[KK * MM];  // fallback scores_soft sink
__device__ float g_hard[MM * NN];  // fallback scores_hard sink

// ---------------- Kernel 1: fp32 tiled GEMM  S = x @ w_att  (R1-proven) -----
#define BM 64
#define BN 64
#define BK 16
__global__ __launch_bounds__(256) void gemm_kernel(const float* __restrict__ A,
                                                   const float* __restrict__ B,
                                                   int k_base) {
    __shared__ float As[BK][BM + 4];
    __shared__ float Bs[BK][BN];

    const int t  = threadIdx.x;
    const int tx = t & 15;
    const int ty = t >> 4;
    const int bm = k_base + blockIdx.y * BM;
    const int bn = blockIdx.x * BN;

    const int arow = t >> 2;
    const int ac4  = (t & 3) << 2;
    const int brow = t >> 4;
    const int bc4  = (t & 15) << 2;

    float acc[4][4];
#pragma unroll
    for (int i = 0; i < 4; i++)
#pragma unroll
        for (int j = 0; j < 4; j++) acc[i][j] = 0.f;

    for (int kt = 0; kt < MM; kt += BK) {
        float4 av = *(const float4*)&A[(size_t)(bm + arow) * MM + kt + ac4];
        As[ac4 + 0][arow] = av.x;
        As[ac4 + 1][arow] = av.y;
        As[ac4 + 2][arow] = av.z;
        As[ac4 + 3][arow] = av.w;
        *(float4*)&Bs[brow][bc4] =
            *(const float4*)&B[(size_t)(kt + brow) * MM + bn + bc4];
        __syncthreads();

#pragma unroll
        for (int kk = 0; kk < BK; kk++) {
            float4 a = *(const float4*)&As[kk][ty << 2];
            float4 b = *(const float4*)&Bs[kk][tx << 2];
            acc[0][0] += a.x * b.x; acc[0][1] += a.x * b.y; acc[0][2] += a.x * b.z; acc[0][3] += a.x * b.w;
            acc[1][0] += a.y * b.x; acc[1][1] += a.y * b.y; acc[1][2] += a.y * b.z; acc[1][3] += a.y * b.w;
            acc[2][0] += a.z * b.x; acc[2][1] += a.z * b.y; acc[2][2] += a.z * b.z; acc[2][3] += a.z * b.w;
            acc[3][0] += a.w * b.x; acc[3][1] += a.w * b.y; acc[3][2] += a.w * b.z; acc[3][3] += a.w * b.w;
        }
        __syncthreads();
    }

#pragma unroll
    for (int i = 0; i < 4; i++) {
        float4 v = make_float4(acc[i][0], acc[i][1], acc[i][2], acc[i][3]);
        *(float4*)&g_S[(size_t)(bm + (ty << 2) + i) * MM + bn + (tx << 2)] = v;
    }
}

// ---------------- Kernel 2: row softmax (+EPS)  (R5-proven) -----------------
__global__ __launch_bounds__(256) void softmax_kernel(float* __restrict__ dst,
                                                      int k_base) {
    const int k   = k_base + blockIdx.x;
    const int tid = threadIdx.x;
    const float* row = g_S + (size_t)k * MM;

    float v0 = row[tid];
    float v1 = row[tid + 256];

    __shared__ float red[256];
    red[tid] = fmaxf(v0, v1);
    __syncthreads();
#pragma unroll
    for (int s = 128; s > 0; s >>= 1) {
        if (tid < s) red[tid] = fmaxf(red[tid], red[tid + s]);
        __syncthreads();
    }
    float mx = red[0];
    __syncthreads();

    float e0 = __expf(v0 - mx);
    float e1 = __expf(v1 - mx);
    red[tid] = e0 + e1;
    __syncthreads();
#pragma unroll
    for (int s = 128; s > 0; s >>= 1) {
        if (tid < s) red[tid] += red[tid + s];
        __syncthreads();
    }
    float inv = 1.f / red[0];

    size_t base = (size_t)k * MM;
    dst[base + tid]       = e0 * inv + EPSV;
    dst[base + tid + 256] = e1 * inv + EPSV;
}

// ---------------- Kernel 3: per-column top-l + hard scores  (R3-proven) -----
__global__ __launch_bounds__(32) void hard_kernel(const float* __restrict__ wb,
                                                  const int* __restrict__ lptr,
                                                  float* __restrict__ dst) {
    const int n    = blockIdx.x;
    const int lane = threadIdx.x;
    int l = lptr ? *lptr : 8;
    if (l < 1) l = 1;
    if (l > LMAX) l = LMAX;

    float v[16];
#pragma unroll
    for (int i = 0; i < 16; i++)
        v[i] = wb[(lane * 16 + i) * NN + n];

    float top[LMAX];
    for (int i = 0; i < l; i++) top[i] = -3.4e38f;
#pragma unroll
    for (int i = 0; i < 16; i++) {
        float x = v[i];
        if (x > top[l - 1]) {
            int j = l - 1;
            while (j > 0 && top[j - 1] < x) { top[j] = top[j - 1]; j--; }
            top[j] = x;
        }
    }

    int ptr = 0;
    float thr = -3.4e38f;
    for (int r = 0; r < l; r++) {
        float cand = (ptr < l) ? top[ptr] : -3.4e38f;
        float m = cand;
#pragma unroll
        for (int off = 16; off > 0; off >>= 1)
            m = fmaxf(m, __shfl_xor_sync(0xffffffffu, m, off));
        unsigned b = __ballot_sync(0xffffffffu, cand == m);
        int src = __ffs(b) - 1;
        if (lane == src) ptr++;
        thr = m;
    }

#pragma unroll
    for (int i = 0; i < 16; i++) {
        float sh = v[i] - thr + EPSV;
        sh = fminf(fmaxf(sh, -1.f), 1.f);
        float h = (sh + 1.f) * 0.5f;
        dst[(lane * 16 + i) * NN + n] = h;
    }
}

// ---------------- Kernel 4: epilogue  (R5-proven EXACT, chunk offset) -------
// 16 threads per (k,m); each owns one float4 of n. Plain .wb stores.
__global__ __launch_bounds__(256) void epilogue_kernel(const float* __restrict__ x,
                                                       const float* __restrict__ soft,
                                                       const float* __restrict__ hard,
                                                       float* __restrict__ out,
                                                       float* __restrict__ mw,
                                                       int km_base) {
    const int idx = blockIdx.x * blockDim.x + threadIdx.x;  // 0 .. KCH*MM*16-1
    const int n4  = idx & 15;
    const int km  = km_base + (idx >> 4);   // global (k,m) index
    const int m   = km & (MM - 1);

    float ss = __ldg(&soft[km]);
    float xv = __ldg(&x[km]);
    float4 h = __ldg((const float4*)(hard + m * NN + (n4 << 2)));

    float4 mw4 = make_float4(h.x * ss, h.y * ss, h.z * ss, h.w * ss);
    float4 o4  = make_float4(mw4.x * xv, mw4.y * xv, mw4.z * xv, mw4.w * xv);

    size_t base = (size_t)km * NN + (n4 << 2);
    *(float4*)&out[base] = o4;
    if (mw) *(float4*)&mw[base] = mw4;
}

// ---------------- launch: chunked forked-stream pipeline --------------------
extern "C" void kernel_launch(void* const* d_in, const int* in_sizes, int n_in,
                              void* d_out, int out_size) {
    const float* x     = (const float*)d_in[0];
    const float* w_att = (const float*)d_in[1];
    const float* w_b   = (const float*)d_in[2];
    const int*   lptr  = (n_in > 3) ? (const int*)d_in[3] : nullptr;

    const long SZ_OUT  = (long)KK * MM * NN;
    const long SZ_HARD = (long)MM * NN;
    const long SZ_SOFT = (long)KK * MM;

    float* out_ptr = (float*)d_out;
    float* hard_dst;
    float* soft_dst;
    float* mw_ptr = nullptr;
    if ((long)out_size >= SZ_OUT + SZ_HARD + SZ_SOFT + SZ_OUT) {
        hard_dst = out_ptr + SZ_OUT;
        soft_dst = hard_dst + SZ_HARD;
        mw_ptr   = soft_dst + SZ_SOFT;
    } else {
        float* dummy;
        cudaGetSymbolAddress((void**)&dummy, g_hard);
        hard_dst = dummy;
        cudaGetSymbolAddress((void**)&dummy, g_soft);
        soft_dst = dummy;
    }

    // fork a second stream off the (possibly captured) legacy stream
    cudaStream_t s2;
    cudaStreamCreateWithFlags(&s2, cudaStreamNonBlocking);
    cudaEvent_t evRoot, ev[NCHUNK];
    cudaEventCreateWithFlags(&evRoot, cudaEventDisableTiming);
    for (int i = 0; i < NCHUNK; i++)
        cudaEventCreateWithFlags(&ev[i], cudaEventDisableTiming);

    cudaEventRecord(evRoot, 0);
    cudaStreamWaitEvent(s2, evRoot, 0);

    // s2: per chunk, GEMM then softmax, then record the chunk event
    dim3 ggrid(MM / BN, KCH / BM);        // (8, 8) = 64 blocks per chunk
    for (int i = 0; i < NCHUNK; i++) {
        gemm_kernel<<<ggrid, 256, 0, s2>>>(x, w_att, i * KCH);
        softmax_kernel<<<KCH, 256, 0, s2>>>(soft_dst, i * KCH);
        cudaEventRecord(ev[i], s2);
    }

    // legacy: hard scores run concurrently with chunk 0's GEMM
    hard_kernel<<<NN, 32>>>(w_b, lptr, hard_dst);

    // legacy: epilogue chunk i gated on chunk i's softmax
    const int blocks_per_chunk = (KCH * MM * 16) / 256;   // 16384
    for (int i = 0; i < NCHUNK; i++) {
        cudaStreamWaitEvent(0, ev[i], 0);
        epilogue_kernel<<<blocks_per_chunk, 256>>>(x, soft_dst, hard_dst,
                                                   out_ptr, mw_ptr, i * KCH * MM);
    }
    // s2/events intentionally not destroyed: destroying objects that are part
    // of an active capture is illegal; kernel_launch runs only a handful of
    // times (correctness + capture), so the leak is bounded.
}

// round 10
// speedup vs baseline: 1.0713x; 1.0713x over previous
#include <cuda_runtime.h>
#include <cuda_bf16.h>

// Problem shapes (fixed by dataset)
#define KK 2048   // batch/k dim
#define MM 512    // feature dim m
#define NN 64     // target dim n
#define EPSV 1e-8f
#define LMAX 32

// ---------------- scratch (static device globals; no allocation) ----------------
__device__ float g_S[KK * MM];     // logits x @ w_att
__device__ float g_soft[KK * MM];  // fallback scores_soft sink
__device__ float g_hard[MM * NN];  // fallback scores_hard sink

// ---------------- Kernel 1: GEMM (R1-proven) + hard scores, block-specialized
// Blocks 0..255: 64x64 fp32 GEMM tiles of S = x @ w_att.
// Blocks 256..263: top-l threshold + scores_hard, one warp per n-column.
#define BM 64
#define BN 64
#define BK 16
__global__ __launch_bounds__(256) void gemm_hard_kernel(const float* __restrict__ A,
                                                        const float* __restrict__ B,
                                                        const float* __restrict__ wb,
                                                        const int* __restrict__ lptr,
                                                        float* __restrict__ hard_dst) {
    const int bid = blockIdx.x;
    if (bid < 256) {
        // ---------------- GEMM tile (R1-proven geometry) ----------------
        __shared__ float As[BK][BM + 4];
        __shared__ float Bs[BK][BN];

        const int t  = threadIdx.x;
        const int tx = t & 15;
        const int ty = t >> 4;
        const int bm = (bid >> 3) * BM;   // 32 tiles over k
        const int bn = (bid & 7) * BN;    // 8 tiles over m

        const int arow = t >> 2;
        const int ac4  = (t & 3) << 2;
        const int brow = t >> 4;
        const int bc4  = (t & 15) << 2;

        float acc[4][4];
#pragma unroll
        for (int i = 0; i < 4; i++)
#pragma unroll
            for (int j = 0; j < 4; j++) acc[i][j] = 0.f;

        for (int kt = 0; kt < MM; kt += BK) {
            float4 av = *(const float4*)&A[(size_t)(bm + arow) * MM + kt + ac4];
            As[ac4 + 0][arow] = av.x;
            As[ac4 + 1][arow] = av.y;
            As[ac4 + 2][arow] = av.z;
            As[ac4 + 3][arow] = av.w;
            *(float4*)&Bs[brow][bc4] =
                *(const float4*)&B[(size_t)(kt + brow) * MM + bn + bc4];
            __syncthreads();

#pragma unroll
            for (int kk = 0; kk < BK; kk++) {
                float4 a = *(const float4*)&As[kk][ty << 2];
                float4 b = *(const float4*)&Bs[kk][tx << 2];
                acc[0][0] += a.x * b.x; acc[0][1] += a.x * b.y; acc[0][2] += a.x * b.z; acc[0][3] += a.x * b.w;
                acc[1][0] += a.y * b.x; acc[1][1] += a.y * b.y; acc[1][2] += a.y * b.z; acc[1][3] += a.y * b.w;
                acc[2][0] += a.z * b.x; acc[2][1] += a.z * b.y; acc[2][2] += a.z * b.z; acc[2][3] += a.z * b.w;
                acc[3][0] += a.w * b.x; acc[3][1] += a.w * b.y; acc[3][2] += a.w * b.z; acc[3][3] += a.w * b.w;
            }
            __syncthreads();
        }

#pragma unroll
        for (int i = 0; i < 4; i++) {
            float4 v = make_float4(acc[i][0], acc[i][1], acc[i][2], acc[i][3]);
            *(float4*)&g_S[(size_t)(bm + (ty << 2) + i) * MM + bn + (tx << 2)] = v;
        }
    } else {
        // ---------------- hard scores: warp per n-column (R3-proven) ------
        const int w    = threadIdx.x >> 5;
        const int lane = threadIdx.x & 31;
        const int n    = (bid - 256) * 8 + w;   // 0..63
        int l = lptr ? *lptr : 8;
        if (l < 1) l = 1;
        if (l > LMAX) l = LMAX;

        float v[16];
#pragma unroll
        for (int i = 0; i < 16; i++)
            v[i] = wb[(lane * 16 + i) * NN + n];

        float top[LMAX];
        for (int i = 0; i < l; i++) top[i] = -3.4e38f;
#pragma unroll
        for (int i = 0; i < 16; i++) {
            float x = v[i];
            if (x > top[l - 1]) {
                int j = l - 1;
                while (j > 0 && top[j - 1] < x) { top[j] = top[j - 1]; j--; }
                top[j] = x;
            }
        }

        int ptr = 0;
        float thr = -3.4e38f;
        for (int r = 0; r < l; r++) {
            float cand = (ptr < l) ? top[ptr] : -3.4e38f;
            float m = cand;
#pragma unroll
            for (int off = 16; off > 0; off >>= 1)
                m = fmaxf(m, __shfl_xor_sync(0xffffffffu, m, off));
            unsigned b = __ballot_sync(0xffffffffu, cand == m);
            int src = __ffs(b) - 1;
            if (lane == src) ptr++;
            thr = m;
        }

#pragma unroll
        for (int i = 0; i < 16; i++) {
            float sh = v[i] - thr + EPSV;
            sh = fminf(fmaxf(sh, -1.f), 1.f);
            float h = (sh + 1.f) * 0.5f;
            hard_dst[(lane * 16 + i) * NN + n] = h;
        }
    }
}

// ---------------- Kernel 2: warp-per-row softmax (+EPS), shuffle-only -------
// 256 blocks x 256 threads; warp w owns row k = bid*8 + w. Lane holds 4
// float4s (cols 4*lane + 128j). No smem, no block barriers.
__global__ __launch_bounds__(256) void softmax_kernel(float* __restrict__ dst) {
    const int w    = threadIdx.x >> 5;
    const int lane = threadIdx.x & 31;
    const int k    = blockIdx.x * 8 + w;
    const float* row = g_S + (size_t)k * MM;

    float4 v[4];
#pragma unroll
    for (int j = 0; j < 4; j++)
        v[j] = __ldg((const float4*)(row + (lane << 2) + 128 * j));

    float mx = -3.4e38f;
#pragma unroll
    for (int j = 0; j < 4; j++)
        mx = fmaxf(mx, fmaxf(fmaxf(v[j].x, v[j].y), fmaxf(v[j].z, v[j].w)));
#pragma unroll
    for (int off = 16; off > 0; off >>= 1)
        mx = fmaxf(mx, __shfl_xor_sync(0xffffffffu, mx, off));

    float sum = 0.f;
#pragma unroll
    for (int j = 0; j < 4; j++) {
        v[j].x = __expf(v[j].x - mx);
        v[j].y = __expf(v[j].y - mx);
        v[j].z = __expf(v[j].z - mx);
        v[j].w = __expf(v[j].w - mx);
        sum += v[j].x + v[j].y + v[j].z + v[j].w;
    }
#pragma unroll
    for (int off = 16; off > 0; off >>= 1)
        sum += __shfl_xor_sync(0xffffffffu, sum, off);
    float inv = 1.f / sum;

    float* drow = dst + (size_t)k * MM;
#pragma unroll
    for (int j = 0; j < 4; j++) {
        float4 s = make_float4(v[j].x * inv + EPSV, v[j].y * inv + EPSV,
                               v[j].z * inv + EPSV, v[j].w * inv + EPSV);
        *(float4*)(drow + (lane << 2) + 128 * j) = s;
    }
}

// ---------------- Kernel 3: epilogue (R5-proven EXACT) ----------------------
// 16 threads per (k,m); each owns one float4 of n. Plain .wb stores.
__global__ __launch_bounds__(256) void epilogue_kernel(const float* __restrict__ x,
                                                       const float* __restrict__ soft,
                                                       const float* __restrict__ hard,
                                                       float* __restrict__ out,
                                                       float* __restrict__ mw) {
    const int idx = blockIdx.x * blockDim.x + threadIdx.x;  // 0 .. KK*MM*16-1
    const int n4  = idx & 15;
    const int km  = idx >> 4;       // 0 .. KK*MM-1
    const int m   = km & (MM - 1);

    float ss = __ldg(&soft[km]);
    float xv = __ldg(&x[km]);
    float4 h = __ldg((const float4*)(hard + m * NN + (n4 << 2)));

    float4 mw4 = make_float4(h.x * ss, h.y * ss, h.z * ss, h.w * ss);
    float4 o4  = make_float4(mw4.x * xv, mw4.y * xv, mw4.z * xv, mw4.w * xv);

    size_t base = (size_t)km * NN + (n4 << 2);
    *(float4*)&out[base] = o4;
    if (mw) *(float4*)&mw[base] = mw4;
}

// ---------------- launch: 3 sequential kernels ------------------------------
extern "C" void kernel_launch(void* const* d_in, const int* in_sizes, int n_in,
                              void* d_out, int out_size) {
    const float* x     = (const float*)d_in[0];
    const float* w_att = (const float*)d_in[1];
    const float* w_b   = (const float*)d_in[2];
    const int*   lptr  = (n_in > 3) ? (const int*)d_in[3] : nullptr;

    const long SZ_OUT  = (long)KK * MM * NN;
    const long SZ_HARD = (long)MM * NN;
    const long SZ_SOFT = (long)KK * MM;

    float* out_ptr = (float*)d_out;
    float* hard_dst;
    float* soft_dst;
    float* mw_ptr = nullptr;
    if ((long)out_size >= SZ_OUT + SZ_HARD + SZ_SOFT + SZ_OUT) {
        hard_dst = out_ptr + SZ_OUT;
        soft_dst = hard_dst + SZ_HARD;
        mw_ptr   = soft_dst + SZ_SOFT;
    } else {
        float* dummy;
        cudaGetSymbolAddress((void**)&dummy, g_hard);
        hard_dst = dummy;
        cudaGetSymbolAddress((void**)&dummy, g_soft);
        soft_dst = dummy;
    }

    gemm_hard_kernel<<<256 + 8, 256>>>(x, w_att, w_b, lptr, hard_dst);

    softmax_kernel<<<KK / 8, 256>>>(soft_dst);

    epilogue_kernel<<<(KK * MM * 16) / 256, 256>>>(x, soft_dst, hard_dst,
                                                   out_ptr, mw_ptr);
}

// round 11
// speedup vs baseline: 1.5345x; 1.4324x over previous
#include <cuda_runtime.h>
#include <cuda_bf16.h>

// Problem shapes (fixed by dataset)
#define KK 2048   // batch/k dim
#define MM 512    // feature dim m
#define NN 64     // target dim n
#define EPSV 1e-8f
#define LMAX 32

// ---------------- scratch (static device globals; no allocation) ----------------
__device__ float g_S[KK * MM];     // logits x @ w_att
__device__ float g_soft[KK * MM];  // fallback scores_soft sink
__device__ float g_hard[MM * NN];  // fallback scores_hard sink

// ---------------- Kernel 1: fp32 tiled GEMM, software-pipelined -------------
// R1-proven 64x64x16 geometry; global->register prefetch added so the LDG
// latency of tile t+1 hides under the 256 FMAs/thread of tile t.
#define BM 64
#define BN 64
#define BK 16
__global__ __launch_bounds__(256) void gemm_kernel(const float* __restrict__ A,
                                                   const float* __restrict__ B) {
    __shared__ float As[BK][BM + 4];
    __shared__ float Bs[BK][BN];

    const int t  = threadIdx.x;
    const int tx = t & 15;
    const int ty = t >> 4;
    const int bm = blockIdx.y * BM;
    const int bn = blockIdx.x * BN;

    const int arow = t >> 2;
    const int ac4  = (t & 3) << 2;
    const int brow = t >> 4;
    const int bc4  = (t & 15) << 2;

    float acc[4][4];
#pragma unroll
    for (int i = 0; i < 4; i++)
#pragma unroll
        for (int j = 0; j < 4; j++) acc[i][j] = 0.f;

    // prefetch tile 0
    float4 av = *(const float4*)&A[(size_t)(bm + arow) * MM + ac4];
    float4 bv = *(const float4*)&B[(size_t)brow * MM + bn + bc4];

    for (int kt = 0; kt < MM; kt += BK) {
        // commit prefetched tile to smem
        As[ac4 + 0][arow] = av.x;
        As[ac4 + 1][arow] = av.y;
        As[ac4 + 2][arow] = av.z;
        As[ac4 + 3][arow] = av.w;
        *(float4*)&Bs[brow][bc4] = bv;
        __syncthreads();

        // prefetch next tile (issues LDG early; retires during compute)
        if (kt + BK < MM) {
            av = *(const float4*)&A[(size_t)(bm + arow) * MM + kt + BK + ac4];
            bv = *(const float4*)&B[(size_t)(kt + BK + brow) * MM + bn + bc4];
        }

#pragma unroll
        for (int kk = 0; kk < BK; kk++) {
            float4 a = *(const float4*)&As[kk][ty << 2];
            float4 b = *(const float4*)&Bs[kk][tx << 2];
            acc[0][0] += a.x * b.x; acc[0][1] += a.x * b.y; acc[0][2] += a.x * b.z; acc[0][3] += a.x * b.w;
            acc[1][0] += a.y * b.x; acc[1][1] += a.y * b.y; acc[1][2] += a.y * b.z; acc[1][3] += a.y * b.w;
            acc[2][0] += a.z * b.x; acc[2][1] += a.z * b.y; acc[2][2] += a.z * b.z; acc[2][3] += a.z * b.w;
            acc[3][0] += a.w * b.x; acc[3][1] += a.w * b.y; acc[3][2] += a.w * b.z; acc[3][3] += a.w * b.w;
        }
        __syncthreads();
    }

#pragma unroll
    for (int i = 0; i < 4; i++) {
        float4 v = make_float4(acc[i][0], acc[i][1], acc[i][2], acc[i][3]);
        *(float4*)&g_S[(size_t)(bm + (ty << 2) + i) * MM + bn + (tx << 2)] = v;
    }
}

// ---------------- Kernel 2: per-column top-l + hard scores  (R3-proven) -----
__global__ __launch_bounds__(32) void hard_kernel(const float* __restrict__ wb,
                                                  const int* __restrict__ lptr,
                                                  float* __restrict__ dst) {
    const int n    = blockIdx.x;
    const int lane = threadIdx.x;
    int l = lptr ? *lptr : 8;
    if (l < 1) l = 1;
    if (l > LMAX) l = LMAX;

    float v[16];
#pragma unroll
    for (int i = 0; i < 16; i++)
        v[i] = wb[(lane * 16 + i) * NN + n];

    float top[LMAX];
    for (int i = 0; i < l; i++) top[i] = -3.4e38f;
#pragma unroll
    for (int i = 0; i < 16; i++) {
        float x = v[i];
        if (x > top[l - 1]) {
            int j = l - 1;
            while (j > 0 && top[j - 1] < x) { top[j] = top[j - 1]; j--; }
            top[j] = x;
        }
    }

    int ptr = 0;
    float thr = -3.4e38f;
    for (int r = 0; r < l; r++) {
        float cand = (ptr < l) ? top[ptr] : -3.4e38f;
        float m = cand;
#pragma unroll
        for (int off = 16; off > 0; off >>= 1)
            m = fmaxf(m, __shfl_xor_sync(0xffffffffu, m, off));
        unsigned b = __ballot_sync(0xffffffffu, cand == m);
        int src = __ffs(b) - 1;
        if (lane == src) ptr++;
        thr = m;
    }

#pragma unroll
    for (int i = 0; i < 16; i++) {
        float sh = v[i] - thr + EPSV;
        sh = fminf(fmaxf(sh, -1.f), 1.f);
        float h = (sh + 1.f) * 0.5f;
        dst[(lane * 16 + i) * NN + n] = h;
    }
}

// ---------------- Kernel 3: warp-per-row softmax, shuffle-only --------------
// 256 blocks x 256 threads; warp w owns row k = bid*8 + w. Lane holds 4
// float4s (cols 4*lane + 128j). No smem, no block barriers.
__global__ __launch_bounds__(256) void softmax_kernel(float* __restrict__ dst) {
    const int w    = threadIdx.x >> 5;
    const int lane = threadIdx.x & 31;
    const int k    = blockIdx.x * 8 + w;
    const float* row = g_S + (size_t)k * MM;

    float4 v[4];
#pragma unroll
    for (int j = 0; j < 4; j++)
        v[j] = __ldg((const float4*)(row + (lane << 2) + 128 * j));

    float mx = -3.4e38f;
#pragma unroll
    for (int j = 0; j < 4; j++)
        mx = fmaxf(mx, fmaxf(fmaxf(v[j].x, v[j].y), fmaxf(v[j].z, v[j].w)));
#pragma unroll
    for (int off = 16; off > 0; off >>= 1)
        mx = fmaxf(mx, __shfl_xor_sync(0xffffffffu, mx, off));

    float sum = 0.f;
#pragma unroll
    for (int j = 0; j < 4; j++) {
        v[j].x = __expf(v[j].x - mx);
        v[j].y = __expf(v[j].y - mx);
        v[j].z = __expf(v[j].z - mx);
        v[j].w = __expf(v[j].w - mx);
        sum += v[j].x + v[j].y + v[j].z + v[j].w;
    }
#pragma unroll
    for (int off = 16; off > 0; off >>= 1)
        sum += __shfl_xor_sync(0xffffffffu, sum, off);
    float inv = 1.f / sum;

    float* drow = dst + (size_t)k * MM;
#pragma unroll
    for (int j = 0; j < 4; j++) {
        float4 s = make_float4(v[j].x * inv + EPSV, v[j].y * inv + EPSV,
                               v[j].z * inv + EPSV, v[j].w * inv + EPSV);
        *(float4*)(drow + (lane << 2) + 128 * j) = s;
    }
}

// ---------------- Kernel 4: epilogue (R5-proven EXACT) ----------------------
// 16 threads per (k,m); each owns one float4 of n. Plain .wb stores.
__global__ __launch_bounds__(256) void epilogue_kernel(const float* __restrict__ x,
                                                       const float* __restrict__ soft,
                                                       const float* __restrict__ hard,
                                                       float* __restrict__ out,
                                                       float* __restrict__ mw) {
    const int idx = blockIdx.x * blockDim.x + threadIdx.x;  // 0 .. KK*MM*16-1
    const int n4  = idx & 15;
    const int km  = idx >> 4;       // 0 .. KK*MM-1
    const int m   = km & (MM - 1);

    float ss = __ldg(&soft[km]);
    float xv = __ldg(&x[km]);
    float4 h = __ldg((const float4*)(hard + m * NN + (n4 << 2)));

    float4 mw4 = make_float4(h.x * ss, h.y * ss, h.z * ss, h.w * ss);
    float4 o4  = make_float4(mw4.x * xv, mw4.y * xv, mw4.z * xv, mw4.w * xv);

    size_t base = (size_t)km * NN + (n4 << 2);
    *(float4*)&out[base] = o4;
    if (mw) *(float4*)&mw[base] = mw4;
}

// ---------------- launch: 4 sequential kernels (R5 structure) ---------------
extern "C" void kernel_launch(void* const* d_in, const int* in_sizes, int n_in,
                              void* d_out, int out_size) {
    const float* x     = (const float*)d_in[0];
    const float* w_att = (const float*)d_in[1];
    const float* w_b   = (const float*)d_in[2];
    const int*   lptr  = (n_in > 3) ? (const int*)d_in[3] : nullptr;

    const long SZ_OUT  = (long)KK * MM * NN;
    const long SZ_HARD = (long)MM * NN;
    const long SZ_SOFT = (long)KK * MM;

    float* out_ptr = (float*)d_out;
    float* hard_dst;
    float* soft_dst;
    float* mw_ptr = nullptr;
    if ((long)out_size >= SZ_OUT + SZ_HARD + SZ_SOFT + SZ_OUT) {
        hard_dst = out_ptr + SZ_OUT;
        soft_dst = hard_dst + SZ_HARD;
        mw_ptr   = soft_dst + SZ_SOFT;
    } else {
        float* dummy;
        cudaGetSymbolAddress((void**)&dummy, g_hard);
        hard_dst = dummy;
        cudaGetSymbolAddress((void**)&dummy, g_soft);
        soft_dst = dummy;
    }

    hard_kernel<<<NN, 32>>>(w_b, lptr, hard_dst);

    dim3 ggrid(MM / BN, KK / BM);
    gemm_kernel<<<ggrid, 256>>>(x, w_att);

    softmax_kernel<<<KK / 8, 256>>>(soft_dst);

    epilogue_kernel<<<(KK * MM * 16) / 256, 256>>>(x, soft_dst, hard_dst,
                                                   out_ptr, mw_ptr);
}